// round 1
// baseline (speedup 1.0000x reference)
#include <cuda_runtime.h>
#include <cuda_bf16.h>
#include <math.h>

// ============================================================================
// EnhancedValueNetwork — unique-input table approach.
// Only x[:, :4] (ints 0..13) feed the network -> 14^4 = 38416 distinct inputs.
// BatchNorm stats = histogram-weighted sums over the unique table.
// ============================================================================

#define UNQ 38416          // 14^4
#define BMAX 524288

// ---- static device scratch (allowed; no runtime allocs) --------------------
__device__ float  g_h1[UNQ * 128];
__device__ float  g_h2[UNQ * 128];
__device__ float  g_h3[UNQ * 64];
__device__ float  g_out_tab[UNQ];
__device__ unsigned short g_idx[BMAX];
__device__ int    g_hist[UNQ];
__device__ double g_sums1[256];   // [0:128) sum, [128:256) sumsq
__device__ double g_sums2[256];
__device__ double g_sums3[128];
__device__ float  g_a1[128], g_c1[128];
__device__ float  g_a2[128], g_c2[128];
__device__ float  g_a3[64],  g_c3[64];

// ---------------------------------------------------------------------------
__global__ void zero_kernel() {
    int i = blockIdx.x * blockDim.x + threadIdx.x;
    int stride = gridDim.x * blockDim.x;
    for (int t = i; t < UNQ; t += stride) g_hist[t] = 0;
    if (i < 256) { g_sums1[i] = 0.0; g_sums2[i] = 0.0; }
    if (i < 128) { g_sums3[i] = 0.0; }
}

// ---------------------------------------------------------------------------
__global__ void hist_kernel(const float* __restrict__ x, int B) {
    int i = blockIdx.x * blockDim.x + threadIdx.x;
    if (i >= B) return;
    float4 v = __ldg(reinterpret_cast<const float4*>(x) + (size_t)i * 4);
    int u = (int)v.x + 14 * (int)v.y + 196 * (int)v.z + 2744 * (int)v.w;
    g_idx[i] = (unsigned short)u;
    atomicAdd(&g_hist[u], 1);
}

// ---------------------------------------------------------------------------
__device__ __forceinline__ float score24(float v) {
    float t = fabsf(v - 24.0f) / 24.0f;
    return 1.0f - fminf(t, 1.0f);
}

// Layer 1: features + h1 = z0 @ W1 + b1.  128 threads/block, 128 rows/block.
__global__ void __launch_bounds__(128) l1_kernel(const float* __restrict__ w1,
                                                 const float* __restrict__ b1) {
    __shared__ float zsh[128][20];   // 16 features, padded to 20
    int tid  = threadIdx.x;
    int base = blockIdx.x * 128;
    int row  = base + tid;

    #pragma unroll
    for (int k = 0; k < 20; k++) zsh[tid][k] = 0.0f;

    if (row < UNQ) {
        int u = row;
        int n0 = u % 14; u /= 14;
        int n1 = u % 14; u /= 14;
        int n2 = u % 14;
        int n3 = u / 14;
        float v0 = (float)n0, v1 = (float)n1, v2 = (float)n2, v3 = (float)n3;
        zsh[tid][0] = v0; zsh[tid][1] = v1; zsh[tid][2] = v2; zsh[tid][3] = v3;

        // stable compaction of nonzeros (matches stable argsort of validity)
        float s0 = 0.f, s1 = 0.f, s2 = 0.f, s3 = 0.f; int m = 0;
        if (v0 != 0.f) { s0 = v0; m = 1; }
        if (v1 != 0.f) { if (m == 0) s0 = v1; else s1 = v1; m++; }
        if (v2 != 0.f) { if (m == 0) s0 = v2; else if (m == 1) s1 = v2; else s2 = v2; m++; }
        if (v3 != 0.f) { if (m == 0) s0 = v3; else if (m == 1) s1 = v3; else if (m == 2) s2 = v3; else s3 = v3; m++; }

        int rank = 0;
        auto emit = [&](float A, float Bv, int q) {
            if (q < m) {
                if (rank < 3) {
                    float* fp = &zsh[tid][4 + rank * 4];
                    fp[0] = score24(A + Bv);
                    fp[1] = score24(A * Bv);
                    fp[2] = score24(A - Bv);
                    fp[3] = score24(A / Bv);
                }
                rank++;
            }
        };
        emit(s0, s1, 1); emit(s0, s2, 2); emit(s0, s3, 3);
        emit(s1, s2, 2); emit(s1, s3, 3); emit(s2, s3, 3);
    }

    // this thread owns output column `tid` for all rows in the block
    float wreg[16];
    #pragma unroll
    for (int k = 0; k < 16; k++) wreg[k] = __ldg(&w1[k * 128 + tid]);
    float bb = __ldg(&b1[tid]);

    __syncthreads();

    int nrows = min(128, UNQ - base);
    for (int r = 0; r < nrows; r++) {
        const float4* zp = reinterpret_cast<const float4*>(&zsh[r][0]);
        float4 a0 = zp[0], a1 = zp[1], a2 = zp[2], a3 = zp[3];
        float acc = bb;
        acc = fmaf(a0.x, wreg[0],  acc); acc = fmaf(a0.y, wreg[1],  acc);
        acc = fmaf(a0.z, wreg[2],  acc); acc = fmaf(a0.w, wreg[3],  acc);
        acc = fmaf(a1.x, wreg[4],  acc); acc = fmaf(a1.y, wreg[5],  acc);
        acc = fmaf(a1.z, wreg[6],  acc); acc = fmaf(a1.w, wreg[7],  acc);
        acc = fmaf(a2.x, wreg[8],  acc); acc = fmaf(a2.y, wreg[9],  acc);
        acc = fmaf(a2.z, wreg[10], acc); acc = fmaf(a2.w, wreg[11], acc);
        acc = fmaf(a3.x, wreg[12], acc); acc = fmaf(a3.y, wreg[13], acc);
        acc = fmaf(a3.z, wreg[14], acc); acc = fmaf(a3.w, wreg[15], acc);
        g_h1[(size_t)(base + r) * 128 + tid] = acc;
    }
}

// ---------------------------------------------------------------------------
// Count-weighted column stats of a table.  L: 0->h1(128), 1->h2(128), 2->h3(64)
template <int L>
__global__ void stats_kernel() {
    constexpr int NC = (L == 2) ? 64 : 128;
    const float* tab = (L == 0) ? g_h1 : (L == 1) ? g_h2 : g_h3;
    double* sums     = (L == 0) ? g_sums1 : (L == 1) ? g_sums2 : g_sums3;

    int col  = threadIdx.x % NC;
    int rpb  = blockDim.x / NC;
    int r0   = blockIdx.x * rpb + threadIdx.x / NC;
    int step = gridDim.x * rpb;

    float s = 0.f, ss = 0.f;
    for (int r = r0; r < UNQ; r += step) {
        float c = (float)g_hist[r];
        float h = tab[(size_t)r * NC + col];
        float ch = c * h;
        s += ch;
        ss = fmaf(ch, h, ss);
    }
    atomicAdd(&sums[col], (double)s);
    atomicAdd(&sums[NC + col], (double)ss);
}

// Finalize BN affine:  a = gamma*rsqrt(var+eps),  c = beta - a*mu
template <int L>
__global__ void fin_kernel(const float* __restrict__ g, const float* __restrict__ be,
                           double invB) {
    constexpr int NC = (L == 2) ? 64 : 128;
    double* sums = (L == 0) ? g_sums1 : (L == 1) ? g_sums2 : g_sums3;
    float* a     = (L == 0) ? g_a1 : (L == 1) ? g_a2 : g_a3;
    float* c     = (L == 0) ? g_c1 : (L == 1) ? g_c2 : g_c3;
    int j = threadIdx.x;
    if (j < NC) {
        double mu  = sums[j] * invB;
        double var = sums[NC + j] * invB - mu * mu;
        float aj = g[j] * rsqrtf((float)var + 1e-5f);
        a[j] = aj;
        c[j] = be[j] - aj * (float)mu;
    }
}

// ---------------------------------------------------------------------------
// GEMM: out = relu(a*in + c) @ W + bias over the unique table.
// LAYER 0: h1(128) -> h2(128, W=w2).  LAYER 1: h2(128) -> h3(64, W=w3).
// 256 threads; tile 64 rows x NOUT cols; thread tile 4 rows x (NOUT/16) cols.
template <int LAYER>
__global__ void __launch_bounds__(256) gemm_kernel(const float* __restrict__ W,
                                                   const float* __restrict__ bias) {
    constexpr int NOUT = (LAYER == 0) ? 128 : 64;
    constexpr int CPT  = NOUT / 16;
    const float* in_tab  = (LAYER == 0) ? g_h1 : g_h2;
    float*       out_tab = (LAYER == 0) ? g_h2 : g_h3;
    const float* asc     = (LAYER == 0) ? g_a1 : g_a2;
    const float* csc     = (LAYER == 0) ? g_c1 : g_c2;

    __shared__ float zsh[64][132];

    int tid   = threadIdx.x;
    int base  = blockIdx.x * 64;
    int nrows = min(64, UNQ - base);

    // stage z tile = relu(a*h + c), zero-pad tail rows
    #pragma unroll 4
    for (int l = tid; l < 64 * 128; l += 256) {
        int r = l >> 7, k = l & 127;
        float v = 0.0f;
        if (r < nrows)
            v = fmaxf(fmaf(__ldg(&asc[k]), in_tab[(size_t)(base + r) * 128 + k],
                           __ldg(&csc[k])), 0.0f);
        zsh[r][k] = v;
    }
    __syncthreads();

    int tx = tid & 15;        // col group
    int ty = tid >> 4;        // row group

    float acc[4][CPT];
    #pragma unroll
    for (int i = 0; i < 4; i++)
        #pragma unroll
        for (int j = 0; j < CPT; j++) acc[i][j] = 0.0f;

    const float4* wptr = reinterpret_cast<const float4*>(W) + (tx * CPT) / 4;
    constexpr int WSTRIDE = NOUT / 4;   // float4s per k-row

    #pragma unroll 4
    for (int k = 0; k < 128; k++) {
        float zr[4];
        #pragma unroll
        for (int i = 0; i < 4; i++) zr[i] = zsh[ty * 4 + i][k];

        float4 wa = __ldg(wptr + (size_t)k * WSTRIDE);
        float wv[CPT];
        wv[0] = wa.x; wv[1] = wa.y; wv[2] = wa.z; wv[3] = wa.w;
        if (CPT == 8) {
            float4 wb = __ldg(wptr + (size_t)k * WSTRIDE + 1);
            wv[4] = wb.x; wv[5] = wb.y; wv[6] = wb.z; wv[7] = wb.w;
        }
        #pragma unroll
        for (int i = 0; i < 4; i++)
            #pragma unroll
            for (int j = 0; j < CPT; j++)
                acc[i][j] = fmaf(zr[i], wv[j], acc[i][j]);
    }

    float bv[CPT];
    #pragma unroll
    for (int j = 0; j < CPT; j++) bv[j] = __ldg(&bias[tx * CPT + j]);

    #pragma unroll
    for (int i = 0; i < 4; i++) {
        int r = ty * 4 + i;
        if (r < nrows) {
            float* op = out_tab + (size_t)(base + r) * NOUT + tx * CPT;
            float4 o0 = make_float4(acc[i][0] + bv[0], acc[i][1] + bv[1],
                                    acc[i][2] + bv[2], acc[i][3] + bv[3]);
            reinterpret_cast<float4*>(op)[0] = o0;
            if (CPT == 8) {
                float4 o1 = make_float4(acc[i][4] + bv[4], acc[i][5] + bv[5],
                                        acc[i][6] + bv[6], acc[i][7] + bv[7]);
                reinterpret_cast<float4*>(op)[1] = o1;
            }
        }
    }
}

// ---------------------------------------------------------------------------
__global__ void l4_kernel(const float* __restrict__ w4, const float* __restrict__ b4) {
    int u = blockIdx.x * blockDim.x + threadIdx.x;
    if (u >= UNQ) return;
    const float4* hr = reinterpret_cast<const float4*>(g_h3 + (size_t)u * 64);
    float acc = __ldg(b4);
    #pragma unroll
    for (int q = 0; q < 16; q++) {
        float4 h = hr[q];
        int k = q * 4;
        float z0 = fmaxf(fmaf(g_a3[k + 0], h.x, g_c3[k + 0]), 0.0f);
        float z1 = fmaxf(fmaf(g_a3[k + 1], h.y, g_c3[k + 1]), 0.0f);
        float z2 = fmaxf(fmaf(g_a3[k + 2], h.z, g_c3[k + 2]), 0.0f);
        float z3 = fmaxf(fmaf(g_a3[k + 3], h.w, g_c3[k + 3]), 0.0f);
        acc = fmaf(z0, __ldg(&w4[k + 0]), acc);
        acc = fmaf(z1, __ldg(&w4[k + 1]), acc);
        acc = fmaf(z2, __ldg(&w4[k + 2]), acc);
        acc = fmaf(z3, __ldg(&w4[k + 3]), acc);
    }
    g_out_tab[u] = 1.0f / (1.0f + expf(-acc));
}

// ---------------------------------------------------------------------------
__global__ void gather_kernel(float* __restrict__ out, int B) {
    int i = blockIdx.x * blockDim.x + threadIdx.x;
    if (i >= B) return;
    out[i] = g_out_tab[g_idx[i]];
}

// ============================================================================
extern "C" void kernel_launch(void* const* d_in, const int* in_sizes, int n_in,
                              void* d_out, int out_size) {
    const float* x   = (const float*)d_in[0];
    const float* w1  = (const float*)d_in[1];
    const float* b1  = (const float*)d_in[2];
    const float* g1  = (const float*)d_in[3];
    const float* be1 = (const float*)d_in[4];
    const float* w2  = (const float*)d_in[5];
    const float* b2  = (const float*)d_in[6];
    const float* g2  = (const float*)d_in[7];
    const float* be2 = (const float*)d_in[8];
    const float* w3  = (const float*)d_in[9];
    const float* b3  = (const float*)d_in[10];
    const float* g3  = (const float*)d_in[11];
    const float* be3 = (const float*)d_in[12];
    const float* w4  = (const float*)d_in[13];
    const float* b4  = (const float*)d_in[14];
    float* out = (float*)d_out;

    int B = in_sizes[0] / 16;
    double invB = 1.0 / (double)B;

    zero_kernel<<<64, 256>>>();
    hist_kernel<<<(B + 255) / 256, 256>>>(x, B);
    l1_kernel<<<(UNQ + 127) / 128, 128>>>(w1, b1);

    stats_kernel<0><<<296, 256>>>();
    fin_kernel<0><<<1, 128>>>(g1, be1, invB);

    gemm_kernel<0><<<(UNQ + 63) / 64, 256>>>(w2, b2);

    stats_kernel<1><<<296, 256>>>();
    fin_kernel<1><<<1, 128>>>(g2, be2, invB);

    gemm_kernel<1><<<(UNQ + 63) / 64, 256>>>(w3, b3);

    stats_kernel<2><<<296, 256>>>();
    fin_kernel<2><<<1, 64>>>(g3, be3, invB);

    l4_kernel<<<(UNQ + 255) / 256, 256>>>(w4, b4);
    gather_kernel<<<(B + 255) / 256, 256>>>(out, B);
}

// round 2
// speedup vs baseline: 1.2980x; 1.2980x over previous
#include <cuda_runtime.h>
#include <cuda_bf16.h>
#include <math.h>

// ============================================================================
// EnhancedValueNetwork — unique-input table approach, stats fused into
// producers, BN-finalize inlined into consumers.  7 kernels total.
// Only x[:, :4] (ints 0..13) matter -> 14^4 = 38416 distinct inputs.
// ============================================================================

#define UNQ 38416          // 14^4
#define BMAX 524288

// ---- static device scratch -------------------------------------------------
__device__ float  g_h1[UNQ * 128];
__device__ float  g_h2[UNQ * 128];
__device__ float  g_h3[UNQ * 64];
__device__ float  g_out_tab[UNQ];
__device__ unsigned short g_idx[BMAX];
__device__ int    g_hist[UNQ];
__device__ double g_sums1[256];   // [0:128) sum, [128:256) sumsq
__device__ double g_sums2[256];
__device__ double g_sums3[128];

// ---------------------------------------------------------------------------
__global__ void zero_kernel() {
    int i = blockIdx.x * blockDim.x + threadIdx.x;
    int stride = gridDim.x * blockDim.x;
    for (int t = i; t < UNQ; t += stride) g_hist[t] = 0;
    if (i < 256) { g_sums1[i] = 0.0; g_sums2[i] = 0.0; }
    if (i < 128) { g_sums3[i] = 0.0; }
}

// ---------------------------------------------------------------------------
__global__ void hist_kernel(const float* __restrict__ x, int B) {
    int i = blockIdx.x * blockDim.x + threadIdx.x;
    if (i >= B) return;
    float4 v = __ldg(reinterpret_cast<const float4*>(x) + (size_t)i * 4);
    int u = (int)v.x + 14 * (int)v.y + 196 * (int)v.z + 2744 * (int)v.w;
    g_idx[i] = (unsigned short)u;
    atomicAdd(&g_hist[u], 1);
}

// ---------------------------------------------------------------------------
__device__ __forceinline__ float score24(float v) {
    float t = fabsf(v - 24.0f) / 24.0f;
    return 1.0f - fminf(t, 1.0f);
}

// Layer 1: features + h1 = z0 @ W1 + b1, with fused weighted column stats.
// 128 threads/block, 128 rows/block; thread tid owns output column tid.
__global__ void __launch_bounds__(128) l1_kernel(const float* __restrict__ w1,
                                                 const float* __restrict__ b1) {
    __shared__ float zsh[128][20];   // 16 features, padded to 20
    __shared__ float cnt_sh[128];
    int tid  = threadIdx.x;
    int base = blockIdx.x * 128;
    int row  = base + tid;

    #pragma unroll
    for (int k = 0; k < 20; k++) zsh[tid][k] = 0.0f;
    cnt_sh[tid] = (row < UNQ) ? (float)__ldg(&g_hist[row]) : 0.0f;

    if (row < UNQ) {
        int u = row;
        int n0 = u % 14; u /= 14;
        int n1 = u % 14; u /= 14;
        int n2 = u % 14;
        int n3 = u / 14;
        float v0 = (float)n0, v1 = (float)n1, v2 = (float)n2, v3 = (float)n3;
        zsh[tid][0] = v0; zsh[tid][1] = v1; zsh[tid][2] = v2; zsh[tid][3] = v3;

        // stable compaction of nonzeros (matches stable argsort of validity)
        float s0 = 0.f, s1 = 0.f, s2 = 0.f, s3 = 0.f; int m = 0;
        if (v0 != 0.f) { s0 = v0; m = 1; }
        if (v1 != 0.f) { if (m == 0) s0 = v1; else s1 = v1; m++; }
        if (v2 != 0.f) { if (m == 0) s0 = v2; else if (m == 1) s1 = v2; else s2 = v2; m++; }
        if (v3 != 0.f) { if (m == 0) s0 = v3; else if (m == 1) s1 = v3; else if (m == 2) s2 = v3; else s3 = v3; m++; }

        int rank = 0;
        auto emit = [&](float A, float Bv, int q) {
            if (q < m) {
                if (rank < 3) {
                    float* fp = &zsh[tid][4 + rank * 4];
                    fp[0] = score24(A + Bv);
                    fp[1] = score24(A * Bv);
                    fp[2] = score24(A - Bv);
                    fp[3] = score24(A / Bv);
                }
                rank++;
            }
        };
        emit(s0, s1, 1); emit(s0, s2, 2); emit(s0, s3, 3);
        emit(s1, s2, 2); emit(s1, s3, 3); emit(s2, s3, 3);
    }

    float wreg[16];
    #pragma unroll
    for (int k = 0; k < 16; k++) wreg[k] = __ldg(&w1[k * 128 + tid]);
    float bb = __ldg(&b1[tid]);

    __syncthreads();

    float s = 0.f, ss = 0.f;
    int nrows = min(128, UNQ - base);
    for (int r = 0; r < nrows; r++) {
        const float4* zp = reinterpret_cast<const float4*>(&zsh[r][0]);
        float4 a0 = zp[0], a1 = zp[1], a2 = zp[2], a3 = zp[3];
        float acc = bb;
        acc = fmaf(a0.x, wreg[0],  acc); acc = fmaf(a0.y, wreg[1],  acc);
        acc = fmaf(a0.z, wreg[2],  acc); acc = fmaf(a0.w, wreg[3],  acc);
        acc = fmaf(a1.x, wreg[4],  acc); acc = fmaf(a1.y, wreg[5],  acc);
        acc = fmaf(a1.z, wreg[6],  acc); acc = fmaf(a1.w, wreg[7],  acc);
        acc = fmaf(a2.x, wreg[8],  acc); acc = fmaf(a2.y, wreg[9],  acc);
        acc = fmaf(a2.z, wreg[10], acc); acc = fmaf(a2.w, wreg[11], acc);
        acc = fmaf(a3.x, wreg[12], acc); acc = fmaf(a3.y, wreg[13], acc);
        acc = fmaf(a3.z, wreg[14], acc); acc = fmaf(a3.w, wreg[15], acc);
        g_h1[(size_t)(base + r) * 128 + tid] = acc;
        float ch = cnt_sh[r] * acc;
        s += ch;
        ss = fmaf(ch, acc, ss);
    }
    atomicAdd(&g_sums1[tid], (double)s);
    atomicAdd(&g_sums1[128 + tid], (double)ss);
}

// ---------------------------------------------------------------------------
// GEMM: out = relu(a*in + c) @ W + bias over the unique table, BN affine
// computed inline from previous layer's sums, output stats fused in epilogue.
// LAYER 0: h1(128)->h2(128, W=w2, stats->g_sums2).
// LAYER 1: h2(128)->h3(64,  W=w3, stats->g_sums3).
template <int LAYER>
__global__ void __launch_bounds__(256) gemm_kernel(const float* __restrict__ W,
                                                   const float* __restrict__ bias,
                                                   const float* __restrict__ gam,
                                                   const float* __restrict__ bet,
                                                   double invB) {
    constexpr int NOUT = (LAYER == 0) ? 128 : 64;
    constexpr int CPT  = NOUT / 16;
    const float*  in_tab   = (LAYER == 0) ? g_h1 : g_h2;
    float*        out_tab  = (LAYER == 0) ? g_h2 : g_h3;
    const double* sums_in  = (LAYER == 0) ? g_sums1 : g_sums2;
    double*       sums_out = (LAYER == 0) ? g_sums2 : g_sums3;

    __shared__ float zsh[64][132];
    __shared__ float a_sh[128], c_sh[128];
    __shared__ float cnt_sh[64];
    __shared__ float psum[NOUT], psum2[NOUT];

    int tid   = threadIdx.x;
    int base  = blockIdx.x * 64;
    int nrows = min(64, UNQ - base);

    // inline BN finalize for input layer
    if (tid < 128) {
        double mu  = sums_in[tid] * invB;
        double var = sums_in[128 + tid] * invB - mu * mu;
        float aj = __ldg(&gam[tid]) * rsqrtf((float)var + 1e-5f);
        a_sh[tid] = aj;
        c_sh[tid] = __ldg(&bet[tid]) - aj * (float)mu;
    }
    if (tid < 64)
        cnt_sh[tid] = (base + tid < UNQ) ? (float)__ldg(&g_hist[base + tid]) : 0.0f;
    if (tid < NOUT) { psum[tid] = 0.0f; psum2[tid] = 0.0f; }
    __syncthreads();

    // stage z tile = relu(a*h + c), zero-pad tail rows
    #pragma unroll 4
    for (int l = tid; l < 64 * 128; l += 256) {
        int r = l >> 7, k = l & 127;
        float v = 0.0f;
        if (r < nrows)
            v = fmaxf(fmaf(a_sh[k], in_tab[(size_t)(base + r) * 128 + k], c_sh[k]), 0.0f);
        zsh[r][k] = v;
    }
    __syncthreads();

    int tx = tid & 15;        // col group
    int ty = tid >> 4;        // row group

    float acc[4][CPT];
    #pragma unroll
    for (int i = 0; i < 4; i++)
        #pragma unroll
        for (int j = 0; j < CPT; j++) acc[i][j] = 0.0f;

    const float4* wptr = reinterpret_cast<const float4*>(W) + (tx * CPT) / 4;
    constexpr int WSTRIDE = NOUT / 4;   // float4s per k-row

    #pragma unroll 4
    for (int k = 0; k < 128; k++) {
        float zr[4];
        #pragma unroll
        for (int i = 0; i < 4; i++) zr[i] = zsh[ty * 4 + i][k];

        float4 wa = __ldg(wptr + (size_t)k * WSTRIDE);
        float wv[CPT];
        wv[0] = wa.x; wv[1] = wa.y; wv[2] = wa.z; wv[3] = wa.w;
        if (CPT == 8) {
            float4 wb = __ldg(wptr + (size_t)k * WSTRIDE + 1);
            wv[4] = wb.x; wv[5] = wb.y; wv[6] = wb.z; wv[7] = wb.w;
        }
        #pragma unroll
        for (int i = 0; i < 4; i++)
            #pragma unroll
            for (int j = 0; j < CPT; j++)
                acc[i][j] = fmaf(zr[i], wv[j], acc[i][j]);
    }

    float bv[CPT];
    #pragma unroll
    for (int j = 0; j < CPT; j++) bv[j] = __ldg(&bias[tx * CPT + j]);

    // write outputs + per-thread weighted sums per column
    float s[CPT], ssq[CPT];
    #pragma unroll
    for (int j = 0; j < CPT; j++) { s[j] = 0.0f; ssq[j] = 0.0f; }

    #pragma unroll
    for (int i = 0; i < 4; i++) {
        int r = ty * 4 + i;
        float cnt = cnt_sh[r];
        float v[CPT];
        #pragma unroll
        for (int j = 0; j < CPT; j++) {
            v[j] = acc[i][j] + bv[j];
            float cv = cnt * v[j];
            s[j] += cv;
            ssq[j] = fmaf(cv, v[j], ssq[j]);
        }
        if (r < nrows) {
            float* op = out_tab + (size_t)(base + r) * NOUT + tx * CPT;
            reinterpret_cast<float4*>(op)[0] = make_float4(v[0], v[1], v[2], v[3]);
            if (CPT == 8)
                reinterpret_cast<float4*>(op)[1] = make_float4(v[4], v[5], v[6], v[7]);
        }
    }

    // reduce across the 16 ty-groups via shared atomics, then 1 global atomic/col
    #pragma unroll
    for (int j = 0; j < CPT; j++) {
        atomicAdd(&psum[tx * CPT + j], s[j]);
        atomicAdd(&psum2[tx * CPT + j], ssq[j]);
    }
    __syncthreads();
    if (tid < NOUT) {
        atomicAdd(&sums_out[tid], (double)psum[tid]);
        atomicAdd(&sums_out[NOUT + tid], (double)psum2[tid]);
    }
}

// ---------------------------------------------------------------------------
__global__ void __launch_bounds__(256) l4_kernel(const float* __restrict__ w4,
                                                 const float* __restrict__ b4,
                                                 const float* __restrict__ g3,
                                                 const float* __restrict__ be3,
                                                 double invB) {
    __shared__ float a_sh[64], c_sh[64];
    int tid = threadIdx.x;
    if (tid < 64) {
        double mu  = g_sums3[tid] * invB;
        double var = g_sums3[64 + tid] * invB - mu * mu;
        float aj = __ldg(&g3[tid]) * rsqrtf((float)var + 1e-5f);
        a_sh[tid] = aj;
        c_sh[tid] = __ldg(&be3[tid]) - aj * (float)mu;
    }
    __syncthreads();

    int u = blockIdx.x * blockDim.x + tid;
    if (u >= UNQ) return;
    const float4* hr = reinterpret_cast<const float4*>(g_h3 + (size_t)u * 64);
    float acc = __ldg(b4);
    #pragma unroll
    for (int q = 0; q < 16; q++) {
        float4 h = hr[q];
        int k = q * 4;
        float z0 = fmaxf(fmaf(a_sh[k + 0], h.x, c_sh[k + 0]), 0.0f);
        float z1 = fmaxf(fmaf(a_sh[k + 1], h.y, c_sh[k + 1]), 0.0f);
        float z2 = fmaxf(fmaf(a_sh[k + 2], h.z, c_sh[k + 2]), 0.0f);
        float z3 = fmaxf(fmaf(a_sh[k + 3], h.w, c_sh[k + 3]), 0.0f);
        acc = fmaf(z0, __ldg(&w4[k + 0]), acc);
        acc = fmaf(z1, __ldg(&w4[k + 1]), acc);
        acc = fmaf(z2, __ldg(&w4[k + 2]), acc);
        acc = fmaf(z3, __ldg(&w4[k + 3]), acc);
    }
    g_out_tab[u] = 1.0f / (1.0f + expf(-acc));
}

// ---------------------------------------------------------------------------
__global__ void gather_kernel(float* __restrict__ out, int B) {
    int i = blockIdx.x * blockDim.x + threadIdx.x;
    if (i >= B) return;
    out[i] = g_out_tab[g_idx[i]];
}

// ============================================================================
extern "C" void kernel_launch(void* const* d_in, const int* in_sizes, int n_in,
                              void* d_out, int out_size) {
    const float* x   = (const float*)d_in[0];
    const float* w1  = (const float*)d_in[1];
    const float* b1  = (const float*)d_in[2];
    const float* g1  = (const float*)d_in[3];
    const float* be1 = (const float*)d_in[4];
    const float* w2  = (const float*)d_in[5];
    const float* b2  = (const float*)d_in[6];
    const float* g2  = (const float*)d_in[7];
    const float* be2 = (const float*)d_in[8];
    const float* w3  = (const float*)d_in[9];
    const float* b3  = (const float*)d_in[10];
    const float* g3  = (const float*)d_in[11];
    const float* be3 = (const float*)d_in[12];
    const float* w4  = (const float*)d_in[13];
    const float* b4  = (const float*)d_in[14];
    float* out = (float*)d_out;

    int B = in_sizes[0] / 16;
    double invB = 1.0 / (double)B;

    zero_kernel<<<64, 256>>>();
    hist_kernel<<<(B + 255) / 256, 256>>>(x, B);
    l1_kernel<<<(UNQ + 127) / 128, 128>>>(w1, b1);
    gemm_kernel<0><<<(UNQ + 63) / 64, 256>>>(w2, b2, g1, be1, invB);
    gemm_kernel<1><<<(UNQ + 63) / 64, 256>>>(w3, b3, g2, be2, invB);
    l4_kernel<<<(UNQ + 255) / 256, 256>>>(w4, b4, g3, be3, invB);
    gather_kernel<<<(B + 255) / 256, 256>>>(out, B);
}

// round 3
// speedup vs baseline: 1.3502x; 1.0402x over previous
#include <cuda_runtime.h>
#include <cuda_bf16.h>
#include <math.h>

// ============================================================================
// EnhancedValueNetwork — unique-input table (14^4 = 38416 rows), fused stats,
// register-blocked double-buffered SGEMM for the two 128-K layers.
// ============================================================================

#define UNQ 38416
#define BMAX 524288

__device__ float  g_h1[UNQ * 128];
__device__ float  g_h2[UNQ * 128];
__device__ float  g_h3[UNQ * 64];
__device__ float  g_out_tab[UNQ];
__device__ unsigned short g_idx[BMAX];
__device__ int    g_hist[UNQ];
__device__ double g_sums1[256];
__device__ double g_sums2[256];
__device__ double g_sums3[128];

// ---------------------------------------------------------------------------
__global__ void zero_kernel() {
    int i = blockIdx.x * blockDim.x + threadIdx.x;
    int stride = gridDim.x * blockDim.x;
    for (int t = i; t < UNQ; t += stride) g_hist[t] = 0;
    if (i < 256) { g_sums1[i] = 0.0; g_sums2[i] = 0.0; }
    if (i < 128) { g_sums3[i] = 0.0; }
}

// ---------------------------------------------------------------------------
__global__ void hist_kernel(const float* __restrict__ x, int B) {
    int i = blockIdx.x * blockDim.x + threadIdx.x;
    if (i >= B) return;
    float4 v = __ldg(reinterpret_cast<const float4*>(x) + (size_t)i * 4);
    int u = (int)v.x + 14 * (int)v.y + 196 * (int)v.z + 2744 * (int)v.w;
    g_idx[i] = (unsigned short)u;
    atomicAdd(&g_hist[u], 1);
}

// ---------------------------------------------------------------------------
__device__ __forceinline__ float score24(float v) {
    float t = fabsf(v - 24.0f) / 24.0f;
    return 1.0f - fminf(t, 1.0f);
}

// Layer 1: features + h1 = z0 @ W1 + b1, fused weighted column stats.
__global__ void __launch_bounds__(128) l1_kernel(const float* __restrict__ w1,
                                                 const float* __restrict__ b1) {
    __shared__ float zsh[128][20];
    __shared__ float cnt_sh[128];
    int tid  = threadIdx.x;
    int base = blockIdx.x * 128;
    int row  = base + tid;

    #pragma unroll
    for (int k = 0; k < 20; k++) zsh[tid][k] = 0.0f;
    cnt_sh[tid] = (row < UNQ) ? (float)__ldg(&g_hist[row]) : 0.0f;

    if (row < UNQ) {
        int u = row;
        int n0 = u % 14; u /= 14;
        int n1 = u % 14; u /= 14;
        int n2 = u % 14;
        int n3 = u / 14;
        float v0 = (float)n0, v1 = (float)n1, v2 = (float)n2, v3 = (float)n3;
        zsh[tid][0] = v0; zsh[tid][1] = v1; zsh[tid][2] = v2; zsh[tid][3] = v3;

        float s0 = 0.f, s1 = 0.f, s2 = 0.f, s3 = 0.f; int m = 0;
        if (v0 != 0.f) { s0 = v0; m = 1; }
        if (v1 != 0.f) { if (m == 0) s0 = v1; else s1 = v1; m++; }
        if (v2 != 0.f) { if (m == 0) s0 = v2; else if (m == 1) s1 = v2; else s2 = v2; m++; }
        if (v3 != 0.f) { if (m == 0) s0 = v3; else if (m == 1) s1 = v3; else if (m == 2) s2 = v3; else s3 = v3; m++; }

        int rank = 0;
        auto emit = [&](float A, float Bv, int q) {
            if (q < m) {
                if (rank < 3) {
                    float* fp = &zsh[tid][4 + rank * 4];
                    fp[0] = score24(A + Bv);
                    fp[1] = score24(A * Bv);
                    fp[2] = score24(A - Bv);
                    fp[3] = score24(A / Bv);
                }
                rank++;
            }
        };
        emit(s0, s1, 1); emit(s0, s2, 2); emit(s0, s3, 3);
        emit(s1, s2, 2); emit(s1, s3, 3); emit(s2, s3, 3);
    }

    float wreg[16];
    #pragma unroll
    for (int k = 0; k < 16; k++) wreg[k] = __ldg(&w1[k * 128 + tid]);
    float bb = __ldg(&b1[tid]);

    __syncthreads();

    float s = 0.f, ss = 0.f;
    int nrows = min(128, UNQ - base);
    for (int r = 0; r < nrows; r++) {
        const float4* zp = reinterpret_cast<const float4*>(&zsh[r][0]);
        float4 a0 = zp[0], a1 = zp[1], a2 = zp[2], a3 = zp[3];
        float acc = bb;
        acc = fmaf(a0.x, wreg[0],  acc); acc = fmaf(a0.y, wreg[1],  acc);
        acc = fmaf(a0.z, wreg[2],  acc); acc = fmaf(a0.w, wreg[3],  acc);
        acc = fmaf(a1.x, wreg[4],  acc); acc = fmaf(a1.y, wreg[5],  acc);
        acc = fmaf(a1.z, wreg[6],  acc); acc = fmaf(a1.w, wreg[7],  acc);
        acc = fmaf(a2.x, wreg[8],  acc); acc = fmaf(a2.y, wreg[9],  acc);
        acc = fmaf(a2.z, wreg[10], acc); acc = fmaf(a2.w, wreg[11], acc);
        acc = fmaf(a3.x, wreg[12], acc); acc = fmaf(a3.y, wreg[13], acc);
        acc = fmaf(a3.z, wreg[14], acc); acc = fmaf(a3.w, wreg[15], acc);
        g_h1[(size_t)(base + r) * 128 + tid] = acc;
        float ch = cnt_sh[r] * acc;
        s += ch;
        ss = fmaf(ch, acc, ss);
    }
    atomicAdd(&g_sums1[tid], (double)s);
    atomicAdd(&g_sums1[128 + tid], (double)ss);
}

// ---------------------------------------------------------------------------
// Register-blocked SGEMM over the table: out = relu(a*in + c) @ W + bias,
// BN finalize inlined, output stats fused.
// Block: 128 rows x NOUT cols, 256 threads, k-chunks of 16, double-buffered.
// LAYER 0: h1(128)->h2(128, W=w2).  LAYER 1: h2(128)->h3(64, W=w3).
template <int LAYER>
__global__ void __launch_bounds__(256, 2) gemm_kernel(const float* __restrict__ W,
                                                      const float* __restrict__ bias,
                                                      const float* __restrict__ gam,
                                                      const float* __restrict__ bet,
                                                      double invB) {
    constexpr int NOUT = (LAYER == 0) ? 128 : 64;
    constexpr int TM   = (LAYER == 0) ? 8 : 4;      // rows per thread
    constexpr int TNX  = NOUT / 8;                  // threads along cols (16 / 8)
    constexpr int NW   = NOUT / 64;                 // W float4 loads per thread (2 / 1)

    const float*  in_tab   = (LAYER == 0) ? g_h1 : g_h2;
    float*        out_tab  = (LAYER == 0) ? g_h2 : g_h3;
    const double* sums_in  = (LAYER == 0) ? g_sums1 : g_sums2;
    double*       sums_out = (LAYER == 0) ? g_sums2 : g_sums3;

    __shared__ __align__(16) float zt[2][16][132];   // k-major z tile
    __shared__ __align__(16) float wt[2][16][NOUT];  // k-major W tile
    __shared__ float a_sh[128], c_sh[128], cnt_sh[128];
    __shared__ float psum[NOUT], psum2[NOUT];

    int tid   = threadIdx.x;
    int base  = blockIdx.x * 128;
    int nrows = min(128, UNQ - base);

    if (tid < 128) {
        double mu  = sums_in[tid] * invB;
        double var = sums_in[128 + tid] * invB - mu * mu;
        float aj = __ldg(&gam[tid]) * rsqrtf((float)var + 1e-5f);
        a_sh[tid] = aj;
        c_sh[tid] = __ldg(&bet[tid]) - aj * (float)mu;
        int r = base + tid;
        cnt_sh[tid] = (r < UNQ) ? (float)__ldg(&g_hist[r]) : 0.0f;
    }
    if (tid < NOUT) { psum[tid] = 0.0f; psum2[tid] = 0.0f; }
    __syncthreads();

    // staging roles
    const int zrow = tid & 127;            // row this thread stages
    const int zkq  = tid >> 7;             // handles k-quads {zkq, zkq+2}
    const bool zvalid = (zrow < nrows);
    const float* zsrc = in_tab + (size_t)(base + zrow) * 128;

    // compute roles
    const int tx = tid % TNX;
    const int ty = tid / TNX;

    float4 pz[2];
    float4 pw[NW];

    auto prefetch = [&](int c) {
        #pragma unroll
        for (int q = 0; q < 2; q++) {
            int kq = zkq + 2 * q;
            int kg = c * 16 + kq * 4;      // global k of first element
            float4 v = zvalid ? __ldg(reinterpret_cast<const float4*>(zsrc + kg))
                              : make_float4(0.f, 0.f, 0.f, 0.f);
            v.x = fmaxf(fmaf(a_sh[kg + 0], v.x, c_sh[kg + 0]), 0.0f);
            v.y = fmaxf(fmaf(a_sh[kg + 1], v.y, c_sh[kg + 1]), 0.0f);
            v.z = fmaxf(fmaf(a_sh[kg + 2], v.z, c_sh[kg + 2]), 0.0f);
            v.w = fmaxf(fmaf(a_sh[kg + 3], v.w, c_sh[kg + 3]), 0.0f);
            if (!zvalid) v = make_float4(0.f, 0.f, 0.f, 0.f);
            pz[q] = v;
        }
        #pragma unroll
        for (int q = 0; q < NW; q++) {
            int f  = tid + q * 256;        // float4 id within chunk
            int k  = f / (NOUT / 4);
            int c4 = f % (NOUT / 4);
            pw[q] = __ldg(reinterpret_cast<const float4*>(W + (size_t)(c * 16 + k) * NOUT) + c4);
        }
    };

    auto store_stage = [&](int buf) {
        #pragma unroll
        for (int q = 0; q < 2; q++) {
            int kk = (zkq + 2 * q) * 4;
            zt[buf][kk + 0][zrow] = pz[q].x;
            zt[buf][kk + 1][zrow] = pz[q].y;
            zt[buf][kk + 2][zrow] = pz[q].z;
            zt[buf][kk + 3][zrow] = pz[q].w;
        }
        #pragma unroll
        for (int q = 0; q < NW; q++) {
            int f  = tid + q * 256;
            int k  = f / (NOUT / 4);
            int c4 = f % (NOUT / 4);
            reinterpret_cast<float4*>(&wt[buf][k][0])[c4] = pw[q];
        }
    };

    float acc[TM][8];
    #pragma unroll
    for (int i = 0; i < TM; i++)
        #pragma unroll
        for (int j = 0; j < 8; j++) acc[i][j] = 0.0f;

    prefetch(0);
    store_stage(0);
    __syncthreads();

    for (int c = 0; c < 8; c++) {
        int buf = c & 1;
        if (c < 7) prefetch(c + 1);

        #pragma unroll
        for (int k = 0; k < 16; k++) {
            float zr[TM];
            {
                float4 za = *reinterpret_cast<const float4*>(&zt[buf][k][ty * TM]);
                zr[0] = za.x; zr[1] = za.y; zr[2] = za.z; zr[3] = za.w;
                if (TM == 8) {
                    float4 zb = *reinterpret_cast<const float4*>(&zt[buf][k][ty * TM + 4]);
                    zr[4] = zb.x; zr[5] = zb.y; zr[6] = zb.z; zr[7] = zb.w;
                }
            }
            float wv[8];
            {
                float4 wa = *reinterpret_cast<const float4*>(&wt[buf][k][tx * 8]);
                float4 wb = *reinterpret_cast<const float4*>(&wt[buf][k][tx * 8 + 4]);
                wv[0] = wa.x; wv[1] = wa.y; wv[2] = wa.z; wv[3] = wa.w;
                wv[4] = wb.x; wv[5] = wb.y; wv[6] = wb.z; wv[7] = wb.w;
            }
            #pragma unroll
            for (int i = 0; i < TM; i++)
                #pragma unroll
                for (int j = 0; j < 8; j++)
                    acc[i][j] = fmaf(zr[i], wv[j], acc[i][j]);
        }

        if (c < 7) store_stage(buf ^ 1);
        __syncthreads();
    }

    // epilogue: bias, store, fused weighted stats
    float bv[8];
    {
        float4 b0 = __ldg(reinterpret_cast<const float4*>(bias) + tx * 2);
        float4 b1 = __ldg(reinterpret_cast<const float4*>(bias) + tx * 2 + 1);
        bv[0] = b0.x; bv[1] = b0.y; bv[2] = b0.z; bv[3] = b0.w;
        bv[4] = b1.x; bv[5] = b1.y; bv[6] = b1.z; bv[7] = b1.w;
    }

    float s[8], ssq[8];
    #pragma unroll
    for (int j = 0; j < 8; j++) { s[j] = 0.0f; ssq[j] = 0.0f; }

    #pragma unroll
    for (int i = 0; i < TM; i++) {
        int r = ty * TM + i;
        float cnt = cnt_sh[r];
        float v[8];
        #pragma unroll
        for (int j = 0; j < 8; j++) {
            v[j] = acc[i][j] + bv[j];
            float cv = cnt * v[j];
            s[j] += cv;
            ssq[j] = fmaf(cv, v[j], ssq[j]);
        }
        if (r < nrows) {
            float* op = out_tab + (size_t)(base + r) * NOUT + tx * 8;
            reinterpret_cast<float4*>(op)[0] = make_float4(v[0], v[1], v[2], v[3]);
            reinterpret_cast<float4*>(op)[1] = make_float4(v[4], v[5], v[6], v[7]);
        }
    }

    #pragma unroll
    for (int j = 0; j < 8; j++) {
        atomicAdd(&psum[tx * 8 + j], s[j]);
        atomicAdd(&psum2[tx * 8 + j], ssq[j]);
    }
    __syncthreads();
    if (tid < NOUT) {
        atomicAdd(&sums_out[tid], (double)psum[tid]);
        atomicAdd(&sums_out[NOUT + tid], (double)psum2[tid]);
    }
}

// ---------------------------------------------------------------------------
__global__ void __launch_bounds__(256) l4_kernel(const float* __restrict__ w4,
                                                 const float* __restrict__ b4,
                                                 const float* __restrict__ g3,
                                                 const float* __restrict__ be3,
                                                 double invB) {
    __shared__ float a_sh[64], c_sh[64];
    int tid = threadIdx.x;
    if (tid < 64) {
        double mu  = g_sums3[tid] * invB;
        double var = g_sums3[64 + tid] * invB - mu * mu;
        float aj = __ldg(&g3[tid]) * rsqrtf((float)var + 1e-5f);
        a_sh[tid] = aj;
        c_sh[tid] = __ldg(&be3[tid]) - aj * (float)mu;
    }
    __syncthreads();

    int u = blockIdx.x * blockDim.x + tid;
    if (u >= UNQ) return;
    const float4* hr = reinterpret_cast<const float4*>(g_h3 + (size_t)u * 64);
    float acc = __ldg(b4);
    #pragma unroll
    for (int q = 0; q < 16; q++) {
        float4 h = hr[q];
        int k = q * 4;
        float z0 = fmaxf(fmaf(a_sh[k + 0], h.x, c_sh[k + 0]), 0.0f);
        float z1 = fmaxf(fmaf(a_sh[k + 1], h.y, c_sh[k + 1]), 0.0f);
        float z2 = fmaxf(fmaf(a_sh[k + 2], h.z, c_sh[k + 2]), 0.0f);
        float z3 = fmaxf(fmaf(a_sh[k + 3], h.w, c_sh[k + 3]), 0.0f);
        acc = fmaf(z0, __ldg(&w4[k + 0]), acc);
        acc = fmaf(z1, __ldg(&w4[k + 1]), acc);
        acc = fmaf(z2, __ldg(&w4[k + 2]), acc);
        acc = fmaf(z3, __ldg(&w4[k + 3]), acc);
    }
    g_out_tab[u] = 1.0f / (1.0f + expf(-acc));
}

// ---------------------------------------------------------------------------
__global__ void gather_kernel(float* __restrict__ out, int B) {
    int i = blockIdx.x * blockDim.x + threadIdx.x;
    if (i >= B) return;
    out[i] = g_out_tab[g_idx[i]];
}

// ============================================================================
extern "C" void kernel_launch(void* const* d_in, const int* in_sizes, int n_in,
                              void* d_out, int out_size) {
    const float* x   = (const float*)d_in[0];
    const float* w1  = (const float*)d_in[1];
    const float* b1  = (const float*)d_in[2];
    const float* g1  = (const float*)d_in[3];
    const float* be1 = (const float*)d_in[4];
    const float* w2  = (const float*)d_in[5];
    const float* b2  = (const float*)d_in[6];
    const float* g2  = (const float*)d_in[7];
    const float* be2 = (const float*)d_in[8];
    const float* w3  = (const float*)d_in[9];
    const float* b3  = (const float*)d_in[10];
    const float* g3  = (const float*)d_in[11];
    const float* be3 = (const float*)d_in[12];
    const float* w4  = (const float*)d_in[13];
    const float* b4  = (const float*)d_in[14];
    float* out = (float*)d_out;

    int B = in_sizes[0] / 16;
    double invB = 1.0 / (double)B;

    zero_kernel<<<64, 256>>>();
    hist_kernel<<<(B + 255) / 256, 256>>>(x, B);
    l1_kernel<<<(UNQ + 127) / 128, 128>>>(w1, b1);
    gemm_kernel<0><<<(UNQ + 127) / 128, 256>>>(w2, b2, g1, be1, invB);
    gemm_kernel<1><<<(UNQ + 127) / 128, 256>>>(w3, b3, g2, be2, invB);
    l4_kernel<<<(UNQ + 255) / 256, 256>>>(w4, b4, g3, be3, invB);
    gather_kernel<<<(B + 255) / 256, 256>>>(out, B);
}

// round 4
// speedup vs baseline: 1.4646x; 1.0847x over previous
#include <cuda_runtime.h>
#include <cuda_bf16.h>
#include <math.h>

// ============================================================================
// EnhancedValueNetwork — unique-input table (14^4 = 38416 rows), fused stats,
// packed-f32x2 register-blocked SGEMM (FFMA2) for the two 128-K layers.
// ============================================================================

#define UNQ 38416
#define BMAX 524288

__device__ float  g_h1[UNQ * 128];
__device__ float  g_h2[UNQ * 128];
__device__ float  g_h3[UNQ * 64];
__device__ float  g_out_tab[UNQ];
__device__ unsigned short g_idx[BMAX];
__device__ int    g_hist[UNQ];
__device__ double g_sums1[256];
__device__ double g_sums2[256];
__device__ double g_sums3[128];

// ---- packed f32x2 helpers --------------------------------------------------
__device__ __forceinline__ unsigned long long pk_dup(float w) {
    unsigned long long r;
    unsigned int wi = __float_as_uint(w);
    asm("mov.b64 %0, {%1, %1};" : "=l"(r) : "r"(wi));
    return r;
}
__device__ __forceinline__ void fma2(unsigned long long& d, unsigned long long a,
                                     unsigned long long b) {
    asm("fma.rn.f32x2 %0, %1, %2, %0;" : "+l"(d) : "l"(a), "l"(b));
}
__device__ __forceinline__ void unpk(unsigned long long v, float& lo, float& hi) {
    unsigned int l, h;
    asm("mov.b64 {%0, %1}, %2;" : "=r"(l), "=r"(h) : "l"(v));
    lo = __uint_as_float(l); hi = __uint_as_float(h);
}

// ---------------------------------------------------------------------------
__global__ void zero_kernel() {
    int i = blockIdx.x * blockDim.x + threadIdx.x;
    int stride = gridDim.x * blockDim.x;
    for (int t = i; t < UNQ; t += stride) g_hist[t] = 0;
    if (i < 256) { g_sums1[i] = 0.0; g_sums2[i] = 0.0; }
    if (i < 128) { g_sums3[i] = 0.0; }
}

// ---------------------------------------------------------------------------
__global__ void hist_kernel(const float* __restrict__ x, int B) {
    int i = blockIdx.x * blockDim.x + threadIdx.x;
    if (i >= B) return;
    float4 v = __ldg(reinterpret_cast<const float4*>(x) + (size_t)i * 4);
    int u = (int)v.x + 14 * (int)v.y + 196 * (int)v.z + 2744 * (int)v.w;
    g_idx[i] = (unsigned short)u;
    atomicAdd(&g_hist[u], 1);
}

// ---------------------------------------------------------------------------
__device__ __forceinline__ float score24(float v) {
    float t = fabsf(v - 24.0f) / 24.0f;
    return 1.0f - fminf(t, 1.0f);
}

// Layer 1: features + h1 = z0 @ W1 + b1, fused weighted column stats.
__global__ void __launch_bounds__(128) l1_kernel(const float* __restrict__ w1,
                                                 const float* __restrict__ b1) {
    __shared__ __align__(16) float zsh[128][20];
    __shared__ float cnt_sh[128];
    int tid  = threadIdx.x;
    int base = blockIdx.x * 128;
    int row  = base + tid;

    #pragma unroll
    for (int k = 0; k < 20; k++) zsh[tid][k] = 0.0f;
    cnt_sh[tid] = (row < UNQ) ? (float)__ldg(&g_hist[row]) : 0.0f;

    if (row < UNQ) {
        int u = row;
        int n0 = u % 14; u /= 14;
        int n1 = u % 14; u /= 14;
        int n2 = u % 14;
        int n3 = u / 14;
        float v0 = (float)n0, v1 = (float)n1, v2 = (float)n2, v3 = (float)n3;
        zsh[tid][0] = v0; zsh[tid][1] = v1; zsh[tid][2] = v2; zsh[tid][3] = v3;

        float s0 = 0.f, s1 = 0.f, s2 = 0.f, s3 = 0.f; int m = 0;
        if (v0 != 0.f) { s0 = v0; m = 1; }
        if (v1 != 0.f) { if (m == 0) s0 = v1; else s1 = v1; m++; }
        if (v2 != 0.f) { if (m == 0) s0 = v2; else if (m == 1) s1 = v2; else s2 = v2; m++; }
        if (v3 != 0.f) { if (m == 0) s0 = v3; else if (m == 1) s1 = v3; else if (m == 2) s2 = v3; else s3 = v3; m++; }

        int rank = 0;
        auto emit = [&](float A, float Bv, int q) {
            if (q < m) {
                if (rank < 3) {
                    float* fp = &zsh[tid][4 + rank * 4];
                    fp[0] = score24(A + Bv);
                    fp[1] = score24(A * Bv);
                    fp[2] = score24(A - Bv);
                    fp[3] = score24(A / Bv);
                }
                rank++;
            }
        };
        emit(s0, s1, 1); emit(s0, s2, 2); emit(s0, s3, 3);
        emit(s1, s2, 2); emit(s1, s3, 3); emit(s2, s3, 3);
    }

    // packed weight pairs over k: wp[q] = (w1[2q][tid], w1[2q+1][tid])
    unsigned long long wp[8];
    #pragma unroll
    for (int q = 0; q < 8; q++) {
        float wl = __ldg(&w1[(2 * q) * 128 + tid]);
        float wh = __ldg(&w1[(2 * q + 1) * 128 + tid]);
        unsigned long long r;
        asm("mov.b64 %0, {%1, %2};" : "=l"(r)
            : "r"(__float_as_uint(wl)), "r"(__float_as_uint(wh)));
        wp[q] = r;
    }
    float bb = __ldg(&b1[tid]);

    __syncthreads();

    float s = 0.f, ss = 0.f;
    int nrows = min(128, UNQ - base);
    for (int r = 0; r < nrows; r++) {
        const unsigned long long* zp =
            reinterpret_cast<const unsigned long long*>(&zsh[r][0]);
        unsigned long long accp = 0ull;   // (0.f, 0.f)
        #pragma unroll
        for (int q = 0; q < 8; q++) fma2(accp, zp[q], wp[q]);
        float lo, hi; unpk(accp, lo, hi);
        float acc = bb + lo + hi;
        g_h1[(size_t)(base + r) * 128 + tid] = acc;
        float ch = cnt_sh[r] * acc;
        s += ch;
        ss = fmaf(ch, acc, ss);
    }
    atomicAdd(&g_sums1[tid], (double)s);
    atomicAdd(&g_sums1[128 + tid], (double)ss);
}

// ---------------------------------------------------------------------------
// Packed-f32x2 SGEMM over the table: out = relu(a*in + c) @ W + bias.
// LAYER 0: 128x128 tile, h1->h2 (W=w2).  LAYER 1: 256x64 tile, h2->h3 (W=w3).
// 256 threads, k-chunks of 16, double-buffered, 8 rows x 8 cols per thread
// held as 4 row-pairs of f32x2 accumulators.
template <int LAYER>
__global__ void __launch_bounds__(256, 2) gemm_kernel(const float* __restrict__ W,
                                                      const float* __restrict__ bias,
                                                      const float* __restrict__ gam,
                                                      const float* __restrict__ bet,
                                                      double invB) {
    constexpr int NOUT = (LAYER == 0) ? 128 : 64;
    constexpr int ROWS = (LAYER == 0) ? 128 : 256;
    constexpr int TNX  = NOUT / 8;          // 16 / 8 threads along cols
    constexpr int TPR  = 256 / ROWS;        // staging threads per row: 2 / 1
    constexpr int QPT  = 4 / TPR;           // k-quads staged per thread: 2 / 4
    constexpr int NW   = NOUT / 64;         // W float4 per thread per chunk: 2 / 1
    constexpr int STR  = ROWS + 4;          // zt row stride (16B-aligned)

    const float*  in_tab   = (LAYER == 0) ? g_h1 : g_h2;
    float*        out_tab  = (LAYER == 0) ? g_h2 : g_h3;
    const double* sums_in  = (LAYER == 0) ? g_sums1 : g_sums2;
    double*       sums_out = (LAYER == 0) ? g_sums2 : g_sums3;

    __shared__ __align__(16) float zt[2][16][STR];
    __shared__ __align__(16) float wt[2][16][NOUT];
    __shared__ float a_sh[128], c_sh[128];
    __shared__ float cnt_sh[ROWS];
    __shared__ float psum[NOUT], psum2[NOUT];

    int tid   = threadIdx.x;
    int base  = blockIdx.x * ROWS;
    int nrows = min(ROWS, UNQ - base);

    if (tid < 128) {
        double mu  = sums_in[tid] * invB;
        double var = sums_in[128 + tid] * invB - mu * mu;
        float aj = __ldg(&gam[tid]) * rsqrtf((float)var + 1e-5f);
        a_sh[tid] = aj;
        c_sh[tid] = __ldg(&bet[tid]) - aj * (float)mu;
    }
    #pragma unroll
    for (int r = tid; r < ROWS; r += 256)
        cnt_sh[r] = (base + r < UNQ) ? (float)__ldg(&g_hist[base + r]) : 0.0f;
    if (tid < NOUT) { psum[tid] = 0.0f; psum2[tid] = 0.0f; }
    __syncthreads();

    // staging roles
    const int zrow = tid % ROWS;
    const int zq0  = tid / ROWS;
    const bool zvalid = (zrow < nrows);
    const float* zsrc = in_tab + (size_t)(base + zrow) * 128;

    // compute roles
    const int tx = tid % TNX;
    const int ty = tid / TNX;

    float4 pz[QPT];
    float4 pw[NW];

    auto prefetch = [&](int c) {
        #pragma unroll
        for (int j = 0; j < QPT; j++) {
            int q  = zq0 + j * TPR;
            int kg = c * 16 + q * 4;
            float4 v = zvalid ? __ldg(reinterpret_cast<const float4*>(zsrc + kg))
                              : make_float4(0.f, 0.f, 0.f, 0.f);
            v.x = fmaxf(fmaf(a_sh[kg + 0], v.x, c_sh[kg + 0]), 0.0f);
            v.y = fmaxf(fmaf(a_sh[kg + 1], v.y, c_sh[kg + 1]), 0.0f);
            v.z = fmaxf(fmaf(a_sh[kg + 2], v.z, c_sh[kg + 2]), 0.0f);
            v.w = fmaxf(fmaf(a_sh[kg + 3], v.w, c_sh[kg + 3]), 0.0f);
            if (!zvalid) v = make_float4(0.f, 0.f, 0.f, 0.f);
            pz[j] = v;
        }
        #pragma unroll
        for (int q = 0; q < NW; q++) {
            int f  = tid + q * 256;
            int k  = f / (NOUT / 4);
            int c4 = f % (NOUT / 4);
            pw[q] = __ldg(reinterpret_cast<const float4*>(W + (size_t)(c * 16 + k) * NOUT) + c4);
        }
    };

    auto store_stage = [&](int buf) {
        #pragma unroll
        for (int j = 0; j < QPT; j++) {
            int kk = (zq0 + j * TPR) * 4;
            zt[buf][kk + 0][zrow] = pz[j].x;
            zt[buf][kk + 1][zrow] = pz[j].y;
            zt[buf][kk + 2][zrow] = pz[j].z;
            zt[buf][kk + 3][zrow] = pz[j].w;
        }
        #pragma unroll
        for (int q = 0; q < NW; q++) {
            int f  = tid + q * 256;
            int k  = f / (NOUT / 4);
            int c4 = f % (NOUT / 4);
            reinterpret_cast<float4*>(&wt[buf][k][0])[c4] = pw[q];
        }
    };

    unsigned long long accp[4][8];
    #pragma unroll
    for (int p = 0; p < 4; p++)
        #pragma unroll
        for (int j = 0; j < 8; j++) accp[p][j] = 0ull;

    prefetch(0);
    store_stage(0);
    __syncthreads();

    for (int c = 0; c < 8; c++) {
        int buf = c & 1;
        if (c < 7) prefetch(c + 1);

        #pragma unroll
        for (int k = 0; k < 16; k++) {
            // 4 packed row-pairs of z: rows ty*8 .. ty*8+7
            ulonglong2 za = *reinterpret_cast<const ulonglong2*>(&zt[buf][k][ty * 8]);
            ulonglong2 zb = *reinterpret_cast<const ulonglong2*>(&zt[buf][k][ty * 8 + 4]);
            unsigned long long zp[4] = {za.x, za.y, zb.x, zb.y};

            float4 wa = *reinterpret_cast<const float4*>(&wt[buf][k][tx * 8]);
            float4 wb = *reinterpret_cast<const float4*>(&wt[buf][k][tx * 8 + 4]);
            unsigned long long wd[8];
            wd[0] = pk_dup(wa.x); wd[1] = pk_dup(wa.y);
            wd[2] = pk_dup(wa.z); wd[3] = pk_dup(wa.w);
            wd[4] = pk_dup(wb.x); wd[5] = pk_dup(wb.y);
            wd[6] = pk_dup(wb.z); wd[7] = pk_dup(wb.w);

            #pragma unroll
            for (int p = 0; p < 4; p++)
                #pragma unroll
                for (int j = 0; j < 8; j++)
                    fma2(accp[p][j], zp[p], wd[j]);
        }

        if (c < 7) store_stage(buf ^ 1);
        __syncthreads();
    }

    // epilogue: bias, store, fused weighted stats
    float bv[8];
    {
        float4 b0 = __ldg(reinterpret_cast<const float4*>(bias) + tx * 2);
        float4 b1 = __ldg(reinterpret_cast<const float4*>(bias) + tx * 2 + 1);
        bv[0] = b0.x; bv[1] = b0.y; bv[2] = b0.z; bv[3] = b0.w;
        bv[4] = b1.x; bv[5] = b1.y; bv[6] = b1.z; bv[7] = b1.w;
    }

    float s[8], ssq[8];
    #pragma unroll
    for (int j = 0; j < 8; j++) { s[j] = 0.0f; ssq[j] = 0.0f; }

    #pragma unroll
    for (int p = 0; p < 4; p++) {
        float vlo[8], vhi[8];
        #pragma unroll
        for (int j = 0; j < 8; j++) {
            float lo, hi; unpk(accp[p][j], lo, hi);
            vlo[j] = lo + bv[j];
            vhi[j] = hi + bv[j];
        }
        int r0 = ty * 8 + 2 * p;
        float c0 = cnt_sh[r0], c1 = cnt_sh[r0 + 1];
        #pragma unroll
        for (int j = 0; j < 8; j++) {
            float cv0 = c0 * vlo[j];
            float cv1 = c1 * vhi[j];
            s[j] += cv0 + cv1;
            ssq[j] = fmaf(cv0, vlo[j], ssq[j]);
            ssq[j] = fmaf(cv1, vhi[j], ssq[j]);
        }
        if (r0 < nrows) {
            float* op = out_tab + (size_t)(base + r0) * NOUT + tx * 8;
            reinterpret_cast<float4*>(op)[0] = make_float4(vlo[0], vlo[1], vlo[2], vlo[3]);
            reinterpret_cast<float4*>(op)[1] = make_float4(vlo[4], vlo[5], vlo[6], vlo[7]);
        }
        if (r0 + 1 < nrows) {
            float* op = out_tab + (size_t)(base + r0 + 1) * NOUT + tx * 8;
            reinterpret_cast<float4*>(op)[0] = make_float4(vhi[0], vhi[1], vhi[2], vhi[3]);
            reinterpret_cast<float4*>(op)[1] = make_float4(vhi[4], vhi[5], vhi[6], vhi[7]);
        }
    }

    #pragma unroll
    for (int j = 0; j < 8; j++) {
        atomicAdd(&psum[tx * 8 + j], s[j]);
        atomicAdd(&psum2[tx * 8 + j], ssq[j]);
    }
    __syncthreads();
    if (tid < NOUT) {
        atomicAdd(&sums_out[tid], (double)psum[tid]);
        atomicAdd(&sums_out[NOUT + tid], (double)psum2[tid]);
    }
}

// ---------------------------------------------------------------------------
__global__ void __launch_bounds__(256) l4_kernel(const float* __restrict__ w4,
                                                 const float* __restrict__ b4,
                                                 const float* __restrict__ g3,
                                                 const float* __restrict__ be3,
                                                 double invB) {
    __shared__ float a_sh[64], c_sh[64];
    int tid = threadIdx.x;
    if (tid < 64) {
        double mu  = g_sums3[tid] * invB;
        double var = g_sums3[64 + tid] * invB - mu * mu;
        float aj = __ldg(&g3[tid]) * rsqrtf((float)var + 1e-5f);
        a_sh[tid] = aj;
        c_sh[tid] = __ldg(&be3[tid]) - aj * (float)mu;
    }
    __syncthreads();

    int u = blockIdx.x * blockDim.x + tid;
    if (u >= UNQ) return;
    const float4* hr = reinterpret_cast<const float4*>(g_h3 + (size_t)u * 64);
    float acc = __ldg(b4);
    #pragma unroll
    for (int q = 0; q < 16; q++) {
        float4 h = hr[q];
        int k = q * 4;
        float z0 = fmaxf(fmaf(a_sh[k + 0], h.x, c_sh[k + 0]), 0.0f);
        float z1 = fmaxf(fmaf(a_sh[k + 1], h.y, c_sh[k + 1]), 0.0f);
        float z2 = fmaxf(fmaf(a_sh[k + 2], h.z, c_sh[k + 2]), 0.0f);
        float z3 = fmaxf(fmaf(a_sh[k + 3], h.w, c_sh[k + 3]), 0.0f);
        acc = fmaf(z0, __ldg(&w4[k + 0]), acc);
        acc = fmaf(z1, __ldg(&w4[k + 1]), acc);
        acc = fmaf(z2, __ldg(&w4[k + 2]), acc);
        acc = fmaf(z3, __ldg(&w4[k + 3]), acc);
    }
    g_out_tab[u] = 1.0f / (1.0f + expf(-acc));
}

// ---------------------------------------------------------------------------
__global__ void gather_kernel(float* __restrict__ out, int B) {
    int i = blockIdx.x * blockDim.x + threadIdx.x;
    if (i >= B) return;
    out[i] = g_out_tab[g_idx[i]];
}

// ============================================================================
extern "C" void kernel_launch(void* const* d_in, const int* in_sizes, int n_in,
                              void* d_out, int out_size) {
    const float* x   = (const float*)d_in[0];
    const float* w1  = (const float*)d_in[1];
    const float* b1  = (const float*)d_in[2];
    const float* g1  = (const float*)d_in[3];
    const float* be1 = (const float*)d_in[4];
    const float* w2  = (const float*)d_in[5];
    const float* b2  = (const float*)d_in[6];
    const float* g2  = (const float*)d_in[7];
    const float* be2 = (const float*)d_in[8];
    const float* w3  = (const float*)d_in[9];
    const float* b3  = (const float*)d_in[10];
    const float* g3  = (const float*)d_in[11];
    const float* be3 = (const float*)d_in[12];
    const float* w4  = (const float*)d_in[13];
    const float* b4  = (const float*)d_in[14];
    float* out = (float*)d_out;

    int B = in_sizes[0] / 16;
    double invB = 1.0 / (double)B;

    zero_kernel<<<64, 256>>>();
    hist_kernel<<<(B + 255) / 256, 256>>>(x, B);
    l1_kernel<<<(UNQ + 127) / 128, 128>>>(w1, b1);
    gemm_kernel<0><<<(UNQ + 127) / 128, 256>>>(w2, b2, g1, be1, invB);
    gemm_kernel<1><<<(UNQ + 255) / 256, 256>>>(w3, b3, g2, be2, invB);
    l4_kernel<<<(UNQ + 255) / 256, 256>>>(w4, b4, g3, be3, invB);
    gather_kernel<<<(B + 255) / 256, 256>>>(out, B);
}